// round 5
// baseline (speedup 1.0000x reference)
#include <cuda_runtime.h>
#include <cstdint>

#define N_PED 131072
#define D_IN 256
#define D_OUT 128
#define SEGSZ 64
#define N_SEQ 2048

namespace {
constexpr int W_ST = D_OUT + 8;   // 136 floats: conflict-free B-frag loads
constexpr int H_ST = D_OUT + 4;   // 132 floats: conflict-free A/S-frag loads
constexpr int X_ST = 64 + 4;      // 68
constexpr int S_ST = 64 + 4;      // 68

constexpr int OFF_W = 0;
constexpr int OFF_H = OFF_W + D_IN * W_ST;    // 34816
constexpr int OFF_X = OFF_H + SEGSZ * H_ST;   // +8448
constexpr int OFF_S = OFF_X + SEGSZ * X_ST;   // +4352
constexpr int OFF_B = OFF_S + SEGSZ * S_ST;   // +4352
constexpr int SMEM_FLOATS = OFF_B + D_OUT;    // 52096
constexpr int SMEM_BYTES = SMEM_FLOATS * 4;   // 208384 B < 227KB
} // namespace

__device__ __forceinline__ float tf32r(float x) {
    uint32_t u = __float_as_uint(x);
    asm("cvt.rna.tf32.f32 %0, %1;" : "=r"(u) : "r"(u));
    return __uint_as_float(u);
}

__device__ __forceinline__ void mma8(float* d, const uint32_t* a, const uint32_t* b) {
    asm volatile(
        "mma.sync.aligned.m16n8k8.row.col.f32.tf32.tf32.f32 "
        "{%0,%1,%2,%3}, {%4,%5,%6,%7}, {%8,%9}, {%0,%1,%2,%3};\n"
        : "+f"(d[0]), "+f"(d[1]), "+f"(d[2]), "+f"(d[3])
        : "r"(a[0]), "r"(a[1]), "r"(a[2]), "r"(a[3]), "r"(b[0]), "r"(b[1]));
}

__global__ __launch_bounds__(256, 1)
void attn_hidden_kernel(const float* __restrict__ Xall,
                        const float* __restrict__ Wg,
                        const float* __restrict__ bg,
                        float* __restrict__ out)
{
    extern __shared__ float smem[];
    float* Ws = smem + OFF_W;
    float* hs = smem + OFF_H;
    float* Xs = smem + OFF_X;
    float* Ss = smem + OFF_S;
    float* bs = smem + OFF_B;

    const int tid  = threadIdx.x;
    const int warp = tid >> 5;
    const int lane = tid & 31;
    const int lr   = lane >> 2;  // group id (row within m16n8 tile)
    const int lc   = lane & 3;   // thread in group

    // 2x4 warp grid: GEMM/ctx warp tile = 32 rows x 32 cols
    const int m0  = (warp & 1) * 32;
    const int n0  = (warp >> 1) * 32;
    // S phase (64x64): warp tile = 32 rows x 16 cols
    const int n0s = (warp >> 1) * 16;

    // ---- Load W (tf32-rounded) and b into smem ONCE per CTA ----
    for (int i = tid; i < (D_IN * D_OUT) / 4; i += 256) {
        int row = i >> 5;          // 32 float4 per W row
        int q   = i & 31;
        float4 w4 = reinterpret_cast<const float4*>(Wg + row * D_OUT)[q];
        float4 r4 = make_float4(tf32r(w4.x), tf32r(w4.y), tf32r(w4.z), tf32r(w4.w));
        *reinterpret_cast<float4*>(Ws + row * W_ST + q * 4) = r4;
    }
    if (tid < D_OUT) bs[tid] = bg[tid];
    __syncthreads();

    for (int g = blockIdx.x; g < N_SEQ; g += gridDim.x) {
        const float* Xg = Xall + (size_t)g * SEGSZ * D_IN;

        // ================= GEMM: h = X(64x256) @ W(256x128) =================
        float acc[2][4][4];
        #pragma unroll
        for (int mt = 0; mt < 2; ++mt)
            #pragma unroll
            for (int nt = 0; nt < 4; ++nt)
                #pragma unroll
                for (int i = 0; i < 4; ++i) acc[mt][nt][i] = 0.f;

        // prefetch chunk 0 into regs (16 floats/thread)
        float4 pre[4];
        #pragma unroll
        for (int t = 0; t < 4; ++t) {
            int idx = tid + t * 256;
            int row = idx >> 4, q = idx & 15;
            pre[t] = *reinterpret_cast<const float4*>(Xg + row * D_IN + q * 4);
        }

        for (int kc = 0; kc < 4; ++kc) {
            __syncthreads();   // all warps done reading Xs (prev chunk / prev segment)
            #pragma unroll
            for (int t = 0; t < 4; ++t) {
                int idx = tid + t * 256;
                int row = idx >> 4, q = idx & 15;
                float4 r4 = make_float4(tf32r(pre[t].x), tf32r(pre[t].y),
                                        tf32r(pre[t].z), tf32r(pre[t].w));
                *reinterpret_cast<float4*>(Xs + row * X_ST + q * 4) = r4;
            }
            __syncthreads();   // Xs ready
            if (kc < 3) {      // prefetch next chunk (overlaps with mma below)
                #pragma unroll
                for (int t = 0; t < 4; ++t) {
                    int idx = tid + t * 256;
                    int row = idx >> 4, q = idx & 15;
                    pre[t] = *reinterpret_cast<const float4*>(
                        Xg + row * D_IN + (kc + 1) * 64 + q * 4);
                }
            }
            #pragma unroll
            for (int k8 = 0; k8 < 8; ++k8) {
                const int kl = k8 * 8;
                uint32_t af[2][4];
                #pragma unroll
                for (int mt = 0; mt < 2; ++mt) {
                    const float* p = Xs + (m0 + mt * 16 + lr) * X_ST + kl + lc;
                    af[mt][0] = __float_as_uint(p[0]);
                    af[mt][1] = __float_as_uint(p[8 * X_ST]);
                    af[mt][2] = __float_as_uint(p[4]);
                    af[mt][3] = __float_as_uint(p[8 * X_ST + 4]);
                }
                uint32_t bf[4][2];
                const int kg = kc * 64 + kl + lc;
                #pragma unroll
                for (int nt = 0; nt < 4; ++nt) {
                    const float* p = Ws + kg * W_ST + n0 + nt * 8 + lr;
                    bf[nt][0] = __float_as_uint(p[0]);
                    bf[nt][1] = __float_as_uint(p[4 * W_ST]);
                }
                #pragma unroll
                for (int mt = 0; mt < 2; ++mt)
                    #pragma unroll
                    for (int nt = 0; nt < 4; ++nt)
                        mma8(acc[mt][nt], af[mt], bf[nt]);
            }
        }

        // write h (+bias), tf32-rounded, to smem
        #pragma unroll
        for (int mt = 0; mt < 2; ++mt) {
            #pragma unroll
            for (int nt = 0; nt < 4; ++nt) {
                int row = m0 + mt * 16 + lr;
                int col = n0 + nt * 8 + 2 * lc;
                hs[row * H_ST + col]           = tf32r(acc[mt][nt][0] + bs[col]);
                hs[row * H_ST + col + 1]       = tf32r(acc[mt][nt][1] + bs[col + 1]);
                hs[(row + 8) * H_ST + col]     = tf32r(acc[mt][nt][2] + bs[col]);
                hs[(row + 8) * H_ST + col + 1] = tf32r(acc[mt][nt][3] + bs[col + 1]);
            }
        }
        __syncthreads();

        // ================= S = h @ h^T  (64x64, K=128) =================
        float accS[2][2][4];
        #pragma unroll
        for (int mt = 0; mt < 2; ++mt)
            #pragma unroll
            for (int nt = 0; nt < 2; ++nt)
                #pragma unroll
                for (int i = 0; i < 4; ++i) accS[mt][nt][i] = 0.f;

        #pragma unroll
        for (int k8 = 0; k8 < 16; ++k8) {
            const int kl = k8 * 8;
            uint32_t af[2][4];
            #pragma unroll
            for (int mt = 0; mt < 2; ++mt) {
                const float* p = hs + (m0 + mt * 16 + lr) * H_ST + kl + lc;
                af[mt][0] = __float_as_uint(p[0]);
                af[mt][1] = __float_as_uint(p[8 * H_ST]);
                af[mt][2] = __float_as_uint(p[4]);
                af[mt][3] = __float_as_uint(p[8 * H_ST + 4]);
            }
            uint32_t bf[2][2];
            #pragma unroll
            for (int nt = 0; nt < 2; ++nt) {
                const float* p = hs + (n0s + nt * 8 + lr) * H_ST + kl + lc;
                bf[nt][0] = __float_as_uint(p[0]);
                bf[nt][1] = __float_as_uint(p[4]);
            }
            #pragma unroll
            for (int mt = 0; mt < 2; ++mt)
                #pragma unroll
                for (int nt = 0; nt < 2; ++nt)
                    mma8(accS[mt][nt], af[mt], bf[nt]);
        }
        // store S raw fp32
        #pragma unroll
        for (int mt = 0; mt < 2; ++mt) {
            #pragma unroll
            for (int nt = 0; nt < 2; ++nt) {
                int row = m0 + mt * 16 + lr;
                int col = n0s + nt * 8 + 2 * lc;
                Ss[row * S_ST + col]           = accS[mt][nt][0];
                Ss[row * S_ST + col + 1]       = accS[mt][nt][1];
                Ss[(row + 8) * S_ST + col]     = accS[mt][nt][2];
                Ss[(row + 8) * S_ST + col + 1] = accS[mt][nt][3];
            }
        }
        __syncthreads();

        // ================= softmax (row-wise), in place, P tf32 =================
        {
            const int srow = tid >> 2;      // 64 rows, 4 threads/row
            const int sq   = tid & 3;
            float4* rp = reinterpret_cast<float4*>(Ss + srow * S_ST + sq * 16);
            float v[16];
            #pragma unroll
            for (int j = 0; j < 4; ++j) {
                float4 t = rp[j];
                v[4*j] = t.x; v[4*j+1] = t.y; v[4*j+2] = t.z; v[4*j+3] = t.w;
            }
            float m = v[0];
            #pragma unroll
            for (int i = 1; i < 16; ++i) m = fmaxf(m, v[i]);
            m = fmaxf(m, __shfl_xor_sync(0xffffffffu, m, 1));
            m = fmaxf(m, __shfl_xor_sync(0xffffffffu, m, 2));
            float s = 0.f;
            #pragma unroll
            for (int i = 0; i < 16; ++i) { v[i] = __expf(v[i] - m); s += v[i]; }
            s += __shfl_xor_sync(0xffffffffu, s, 1);
            s += __shfl_xor_sync(0xffffffffu, s, 2);
            const float inv = 1.0f / s;
            #pragma unroll
            for (int j = 0; j < 4; ++j) {
                float4 t = make_float4(tf32r(v[4*j] * inv),   tf32r(v[4*j+1] * inv),
                                       tf32r(v[4*j+2] * inv), tf32r(v[4*j+3] * inv));
                rp[j] = t;
            }
        }
        __syncthreads();

        // ================= ctx = P(64x64) @ h(64x128) =================
        #pragma unroll
        for (int mt = 0; mt < 2; ++mt)
            #pragma unroll
            for (int nt = 0; nt < 4; ++nt)
                #pragma unroll
                for (int i = 0; i < 4; ++i) acc[mt][nt][i] = 0.f;

        #pragma unroll
        for (int k8 = 0; k8 < 8; ++k8) {
            const int kl = k8 * 8;
            uint32_t af[2][4];
            #pragma unroll
            for (int mt = 0; mt < 2; ++mt) {
                const float* p = Ss + (m0 + mt * 16 + lr) * S_ST + kl + lc;
                af[mt][0] = __float_as_uint(p[0]);
                af[mt][1] = __float_as_uint(p[8 * S_ST]);
                af[mt][2] = __float_as_uint(p[4]);
                af[mt][3] = __float_as_uint(p[8 * S_ST + 4]);
            }
            uint32_t bf[4][2];
            #pragma unroll
            for (int nt = 0; nt < 4; ++nt) {
                const float* p = hs + (kl + lc) * H_ST + n0 + nt * 8 + lr;
                bf[nt][0] = __float_as_uint(p[0]);
                bf[nt][1] = __float_as_uint(p[4 * H_ST]);
            }
            #pragma unroll
            for (int mt = 0; mt < 2; ++mt)
                #pragma unroll
                for (int nt = 0; nt < 4; ++nt)
                    mma8(acc[mt][nt], af[mt], bf[nt]);
        }

        // store ctx to gmem (output row = g*64 + s)
        #pragma unroll
        for (int mt = 0; mt < 2; ++mt) {
            #pragma unroll
            for (int nt = 0; nt < 4; ++nt) {
                size_t row = (size_t)g * SEGSZ + m0 + mt * 16 + lr;
                int col = n0 + nt * 8 + 2 * lc;
                float2 v0 = make_float2(acc[mt][nt][0], acc[mt][nt][1]);
                float2 v1 = make_float2(acc[mt][nt][2], acc[mt][nt][3]);
                *reinterpret_cast<float2*>(out + row * D_OUT + col)       = v0;
                *reinterpret_cast<float2*>(out + (row + 8) * D_OUT + col) = v1;
            }
        }
        // next-iteration kc=0 __syncthreads() guards Xs/hs/Ss reuse
    }
}

extern "C" void kernel_launch(void* const* d_in, const int* in_sizes, int n_in,
                              void* d_out, int out_size) {
    (void)in_sizes; (void)n_in; (void)out_size;
    const float* X = (const float*)d_in[0];
    const float* W = (const float*)d_in[1];
    const float* b = (const float*)d_in[2];
    float* out = (float*)d_out;

    cudaFuncSetAttribute(attn_hidden_kernel,
                         cudaFuncAttributeMaxDynamicSharedMemorySize, SMEM_BYTES);
    attn_hidden_kernel<<<148, 256, SMEM_BYTES>>>(X, W, b, out);
}